// round 3
// baseline (speedup 1.0000x reference)
#include <cuda_runtime.h>
#include <math.h>

#define NN 100000
#define NE 3200000
#define NF 128
#define HH 16
#define NC 10

// ---------------- device scratch (no runtime allocation allowed) ----------------
__device__ int   g_deg1[NN];
__device__ int   g_deg2[NN];
__device__ float g_dinv1[NN];
__device__ float g_dinv2[NN];
__device__ __align__(16) float g_y1[NN * 16];   // dinv1[i] * (x @ W1)[i]
__device__ __align__(16) float g_y2[NN * 16];   // dinv2[i] * (x @ W2)[i]
__device__ __align__(16) float g_acc1[NN * 16];
__device__ __align__(16) float g_acc2[NN * 16];
__device__ __align__(16) float g_yz[NN * 12];   // dinv1[i] * (h @ W4)[i], stride 12
__device__ __align__(16) float g_acc3[NN * 12];

// ---------------- zero scratch ----------------
__global__ void k_zero() {
    int i = blockIdx.x * blockDim.x + threadIdx.x;
    int stride = gridDim.x * blockDim.x;
    for (int t = i; t < NN; t += stride) { g_deg1[t] = 0; g_deg2[t] = 0; }
    for (int t = i; t < NN * 16; t += stride) { g_acc1[t] = 0.f; g_acc2[t] = 0.f; }
    for (int t = i; t < NN * 12; t += stride) g_acc3[t] = 0.f;
}

// ---------------- degrees (dst counts; self-loop folded in later as +1) ----------------
__global__ void k_degree(const int* __restrict__ dst1,
                         const int* __restrict__ dst2) {
    int e = blockIdx.x * blockDim.x + threadIdx.x;
    if (e < NE) {
        atomicAdd(&g_deg1[dst1[e]], 1);
    } else if (e < 2 * NE) {
        atomicAdd(&g_deg2[dst2[e - NE]], 1);
    }
}

// ---------------- fused dual GEMM: y1 = dinv1*(x@W1), y2 = dinv2*(x@W2) ----------------
// blockDim = 128, one node per thread, 128-node x tile in padded shared.
__global__ void k_gemm(const float* __restrict__ x,
                       const float* __restrict__ W1,
                       const float* __restrict__ W2) {
    extern __shared__ float s_mem[];
    float* Ws = s_mem;              // [128][32]  (W1 cols 0..15, W2 cols 16..31)
    float* xs = s_mem + NF * 32;    // [128][129] padded

    int tid = threadIdx.x;
    for (int idx = tid; idx < NF * 32; idx += 128) {
        int k = idx >> 5, j = idx & 31;
        Ws[idx] = (j < HH) ? W1[k * HH + j] : W2[k * HH + (j - HH)];
    }
    int nb = blockIdx.x * 128;
    for (int idx = tid; idx < 128 * NF; idx += 128) {
        int node = idx >> 7, k = idx & 127;
        int gi = nb + node;
        xs[node * 129 + k] = (gi < NN) ? x[(size_t)gi * NF + k] : 0.f;
    }
    __syncthreads();

    int i = nb + tid;
    if (i >= NN) return;

    float acc[32];
#pragma unroll
    for (int j = 0; j < 32; j++) acc[j] = 0.f;

    const float* xr = &xs[tid * 129];
#pragma unroll 4
    for (int k = 0; k < NF; k++) {
        float xk = xr[k];
        const float* wrow = &Ws[k * 32];
#pragma unroll
        for (int j = 0; j < 32; j++) acc[j] += xk * wrow[j];
    }

    float d1 = rsqrtf((float)(g_deg1[i] + 1));
    float d2 = rsqrtf((float)(g_deg2[i] + 1));
    g_dinv1[i] = d1;
    g_dinv2[i] = d2;

    float* o1 = &g_y1[(size_t)i * 16];
    float* o2 = &g_y2[(size_t)i * 16];
#pragma unroll
    for (int j = 0; j < 16; j++) {
        o1[j] = d1 * acc[j];
        o2[j] = d2 * acc[16 + j];
    }
}

// ---------------- edge scatter for 16-wide features ----------------
__global__ void k_scatter16(const int* __restrict__ src,
                            const int* __restrict__ dst,
                            int which) {
    int e = blockIdx.x * blockDim.x + threadIdx.x;
    if (e >= NE) return;
    const float* y = which ? g_y2 : g_y1;
    float* acc = which ? g_acc2 : g_acc1;
    int s = src[e], d = dst[e];
    const float4* yr = (const float4*)(y + (size_t)s * 16);
    float* ar = acc + (size_t)d * 16;
#pragma unroll
    for (int q = 0; q < 4; q++) {
        float4 v = yr[q];
        atomicAdd(ar + 4 * q + 0, v.x);
        atomicAdd(ar + 4 * q + 1, v.y);
        atomicAdd(ar + 4 * q + 2, v.z);
        atomicAdd(ar + 4 * q + 3, v.w);
    }
}

// ---------------- combine: relu epilogues, concat, h @ W4, pre-scale by dinv1 ----------------
__global__ void k_combine(const float* __restrict__ b1,
                          const float* __restrict__ b2,
                          const float* __restrict__ W4) {
    __shared__ float sW4[32 * NC];
    __shared__ float sb1[HH], sb2[HH];
    int tid = threadIdx.x;
    for (int t = tid; t < 32 * NC; t += blockDim.x) sW4[t] = W4[t];
    if (tid < HH) { sb1[tid] = b1[tid]; sb2[tid] = b2[tid]; }
    __syncthreads();

    int i = blockIdx.x * blockDim.x + tid;
    if (i >= NN) return;

    float d1 = g_dinv1[i], d2 = g_dinv2[i];
    float h[32];
    const float* a1 = &g_acc1[(size_t)i * 16];
    const float* y1 = &g_y1[(size_t)i * 16];
    const float* a2 = &g_acc2[(size_t)i * 16];
    const float* y2 = &g_y2[(size_t)i * 16];
#pragma unroll
    for (int j = 0; j < 16; j++) {
        h[j]      = fmaxf(d1 * (a1[j] + y1[j]) + sb1[j], 0.f);
        h[16 + j] = fmaxf(d2 * (a2[j] + y2[j]) + sb2[j], 0.f);
    }

    float z[NC];
#pragma unroll
    for (int c = 0; c < NC; c++) z[c] = 0.f;
#pragma unroll
    for (int j = 0; j < 32; j++) {
        float hj = h[j];
#pragma unroll
        for (int c = 0; c < NC; c++) z[c] += hj * sW4[j * NC + c];
    }

    float* o = &g_yz[(size_t)i * 12];
#pragma unroll
    for (int c = 0; c < NC; c++) o[c] = d1 * z[c];
    o[10] = 0.f;
    o[11] = 0.f;
}

// ---------------- edge scatter for 10-wide logits (stride 12) ----------------
__global__ void k_scatter10(const int* __restrict__ src,
                            const int* __restrict__ dst) {
    int e = blockIdx.x * blockDim.x + threadIdx.x;
    if (e >= NE) return;
    int s = src[e], d = dst[e];
    const float* yr = &g_yz[(size_t)s * 12];
    float* ar = &g_acc3[(size_t)d * 12];
#pragma unroll
    for (int c = 0; c < NC; c++) atomicAdd(ar + c, yr[c]);
}

// ---------------- final: conv3 epilogue + log_softmax ----------------
__global__ void k_final(const float* __restrict__ b4, float* __restrict__ out) {
    __shared__ float sb4[NC];
    if (threadIdx.x < NC) sb4[threadIdx.x] = b4[threadIdx.x];
    __syncthreads();
    int i = blockIdx.x * blockDim.x + threadIdx.x;
    if (i >= NN) return;

    float d1 = g_dinv1[i];
    float l[NC];
    const float* a = &g_acc3[(size_t)i * 12];
    const float* y = &g_yz[(size_t)i * 12];
#pragma unroll
    for (int c = 0; c < NC; c++) l[c] = d1 * (a[c] + y[c]) + sb4[c];

    float m = l[0];
#pragma unroll
    for (int c = 1; c < NC; c++) m = fmaxf(m, l[c]);
    float s = 0.f;
#pragma unroll
    for (int c = 0; c < NC; c++) s += expf(l[c] - m);
    float lse = m + logf(s);
#pragma unroll
    for (int c = 0; c < NC; c++) out[(size_t)i * NC + c] = l[c] - lse;
}

// ---------------- launch ----------------
extern "C" void kernel_launch(void* const* d_in, const int* in_sizes, int n_in,
                              void* d_out, int out_size) {
    const float* x  = (const float*)d_in[0];
    const int*   ei = (const int*)d_in[1];   // [2, NE] int32: row0 src, row1 dst
    const int*   tp = (const int*)d_in[2];
    const float* W1 = (const float*)d_in[3];
    const float* b1 = (const float*)d_in[4];
    const float* W2 = (const float*)d_in[5];
    const float* b2 = (const float*)d_in[6];
    const float* W4 = (const float*)d_in[7];
    const float* b4 = (const float*)d_in[8];
    float* out = (float*)d_out;

    k_zero<<<2048, 256>>>();
    k_degree<<<(2 * NE + 255) / 256, 256>>>(ei + NE, tp + NE);

    size_t smem = (size_t)(NF * 32 + 128 * 129) * sizeof(float);  // 82432 B
    cudaFuncSetAttribute(k_gemm, cudaFuncAttributeMaxDynamicSharedMemorySize, (int)smem);
    k_gemm<<<(NN + 127) / 128, 128, smem>>>(x, W1, W2);

    k_scatter16<<<(NE + 255) / 256, 256>>>(ei, ei + NE, 0);
    k_scatter16<<<(NE + 255) / 256, 256>>>(tp, tp + NE, 1);

    k_combine<<<(NN + 255) / 256, 256>>>(b1, b2, W4);

    k_scatter10<<<(NE + 255) / 256, 256>>>(ei, ei + NE);

    k_final<<<(NN + 255) / 256, 256>>>(b4, out);
}

// round 4
// speedup vs baseline: 2.1524x; 2.1524x over previous
#include <cuda_runtime.h>
#include <math.h>

#define NN 100000
#define NE 3200000
#define NF 128
#define HH 16
#define NC 10

// ---------------- device scratch (no runtime allocation allowed) ----------------
__device__ int   g_deg1[NN];
__device__ int   g_deg2[NN];
__device__ float g_dinv1[NN];
__device__ float g_dinv2[NN];
__device__ __align__(16) float g_y1[NN * 16];   // dinv1[i] * (x @ W1)[i]
__device__ __align__(16) float g_y2[NN * 16];   // dinv2[i] * (x @ W2)[i]
__device__ __align__(16) float g_acc1[NN * 16];
__device__ __align__(16) float g_acc2[NN * 16];
__device__ __align__(16) float g_yz[NN * 12];   // dinv1[i] * (h @ W4)[i], stride 12
__device__ __align__(16) float g_acc3[NN * 12];

// 16-byte vector reduction straight to L2 (sm_90+). Address forced to global space.
__device__ __forceinline__ void red_add_v4(float* p, float4 v) {
    asm volatile("red.global.add.v4.f32 [%0], {%1,%2,%3,%4};"
                 :: "l"(__cvta_generic_to_global(p)),
                    "f"(v.x), "f"(v.y), "f"(v.z), "f"(v.w)
                 : "memory");
}

// ---------------- zero scratch ----------------
__global__ void k_zero() {
    int i = blockIdx.x * blockDim.x + threadIdx.x;
    int stride = gridDim.x * blockDim.x;
    for (int t = i; t < NN; t += stride) { g_deg1[t] = 0; g_deg2[t] = 0; }
    for (int t = i; t < NN * 16; t += stride) { g_acc1[t] = 0.f; g_acc2[t] = 0.f; }
    for (int t = i; t < NN * 12; t += stride) g_acc3[t] = 0.f;
}

// ---------------- degrees (dst counts; self-loop folded in later as +1) ----------------
__global__ void k_degree(const int* __restrict__ dst1,
                         const int* __restrict__ dst2) {
    int e = blockIdx.x * blockDim.x + threadIdx.x;
    if (e < NE) {
        atomicAdd(&g_deg1[dst1[e]], 1);
    } else if (e < 2 * NE) {
        atomicAdd(&g_deg2[dst2[e - NE]], 1);
    }
}

// ---------------- fused dual GEMM: y1 = dinv1*(x@W1), y2 = dinv2*(x@W2) ----------------
__global__ void k_gemm(const float* __restrict__ x,
                       const float* __restrict__ W1,
                       const float* __restrict__ W2) {
    extern __shared__ float s_mem[];
    float* Ws = s_mem;              // [128][32]  (W1 cols 0..15, W2 cols 16..31)
    float* xs = s_mem + NF * 32;    // [128][129] padded

    int tid = threadIdx.x;
    for (int idx = tid; idx < NF * 32; idx += 128) {
        int k = idx >> 5, j = idx & 31;
        Ws[idx] = (j < HH) ? W1[k * HH + j] : W2[k * HH + (j - HH)];
    }
    int nb = blockIdx.x * 128;
    for (int idx = tid; idx < 128 * NF; idx += 128) {
        int node = idx >> 7, k = idx & 127;
        int gi = nb + node;
        xs[node * 129 + k] = (gi < NN) ? x[(size_t)gi * NF + k] : 0.f;
    }
    __syncthreads();

    int i = nb + tid;
    if (i >= NN) return;

    float acc[32];
#pragma unroll
    for (int j = 0; j < 32; j++) acc[j] = 0.f;

    const float* xr = &xs[tid * 129];
#pragma unroll 4
    for (int k = 0; k < NF; k++) {
        float xk = xr[k];
        const float* wrow = &Ws[k * 32];
#pragma unroll
        for (int j = 0; j < 32; j++) acc[j] += xk * wrow[j];
    }

    float d1 = rsqrtf((float)(g_deg1[i] + 1));
    float d2 = rsqrtf((float)(g_deg2[i] + 1));
    g_dinv1[i] = d1;
    g_dinv2[i] = d2;

    float* o1 = &g_y1[(size_t)i * 16];
    float* o2 = &g_y2[(size_t)i * 16];
#pragma unroll
    for (int j = 0; j < 16; j++) {
        o1[j] = d1 * acc[j];
        o2[j] = d2 * acc[16 + j];
    }
}

// ---------------- edge scatter for 16-wide features (4 vector reds / edge) --------
__global__ void k_scatter16(const int* __restrict__ src,
                            const int* __restrict__ dst,
                            int which) {
    int e = blockIdx.x * blockDim.x + threadIdx.x;
    if (e >= NE) return;
    const float* y = which ? g_y2 : g_y1;
    float* acc = which ? g_acc2 : g_acc1;
    int s = src[e], d = dst[e];
    const float4* yr = (const float4*)(y + (size_t)s * 16);
    float* ar = acc + (size_t)d * 16;
    float4 v0 = yr[0], v1 = yr[1], v2 = yr[2], v3 = yr[3];
    red_add_v4(ar + 0,  v0);
    red_add_v4(ar + 4,  v1);
    red_add_v4(ar + 8,  v2);
    red_add_v4(ar + 12, v3);
}

// ---------------- combine: relu epilogues, concat, h @ W4, pre-scale by dinv1 -----
__global__ void k_combine(const float* __restrict__ b1,
                          const float* __restrict__ b2,
                          const float* __restrict__ W4) {
    __shared__ float sW4[32 * NC];
    __shared__ float sb1[HH], sb2[HH];
    int tid = threadIdx.x;
    for (int t = tid; t < 32 * NC; t += blockDim.x) sW4[t] = W4[t];
    if (tid < HH) { sb1[tid] = b1[tid]; sb2[tid] = b2[tid]; }
    __syncthreads();

    int i = blockIdx.x * blockDim.x + tid;
    if (i >= NN) return;

    float d1 = g_dinv1[i], d2 = g_dinv2[i];
    float h[32];
    const float* a1 = &g_acc1[(size_t)i * 16];
    const float* y1 = &g_y1[(size_t)i * 16];
    const float* a2 = &g_acc2[(size_t)i * 16];
    const float* y2 = &g_y2[(size_t)i * 16];
#pragma unroll
    for (int j = 0; j < 16; j++) {
        h[j]      = fmaxf(d1 * (a1[j] + y1[j]) + sb1[j], 0.f);
        h[16 + j] = fmaxf(d2 * (a2[j] + y2[j]) + sb2[j], 0.f);
    }

    float z[NC];
#pragma unroll
    for (int c = 0; c < NC; c++) z[c] = 0.f;
#pragma unroll
    for (int j = 0; j < 32; j++) {
        float hj = h[j];
#pragma unroll
        for (int c = 0; c < NC; c++) z[c] += hj * sW4[j * NC + c];
    }

    float* o = &g_yz[(size_t)i * 12];
#pragma unroll
    for (int c = 0; c < NC; c++) o[c] = d1 * z[c];
    o[10] = 0.f;
    o[11] = 0.f;
}

// ---------------- edge scatter for 10-wide logits (3 vector reds / edge) ----------
__global__ void k_scatter10(const int* __restrict__ src,
                            const int* __restrict__ dst) {
    int e = blockIdx.x * blockDim.x + threadIdx.x;
    if (e >= NE) return;
    int s = src[e], d = dst[e];
    const float4* yr = (const float4*)&g_yz[(size_t)s * 12];   // 48B rows, 16B aligned
    float* ar = &g_acc3[(size_t)d * 12];
    float4 v0 = yr[0], v1 = yr[1], v2 = yr[2];
    red_add_v4(ar + 0, v0);
    red_add_v4(ar + 4, v1);
    red_add_v4(ar + 8, v2);   // lanes 10,11 add 0.0f to padding
}

// ---------------- final: conv3 epilogue + log_softmax ----------------
__global__ void k_final(const float* __restrict__ b4, float* __restrict__ out) {
    __shared__ float sb4[NC];
    if (threadIdx.x < NC) sb4[threadIdx.x] = b4[threadIdx.x];
    __syncthreads();
    int i = blockIdx.x * blockDim.x + threadIdx.x;
    if (i >= NN) return;

    float d1 = g_dinv1[i];
    float l[NC];
    const float* a = &g_acc3[(size_t)i * 12];
    const float* y = &g_yz[(size_t)i * 12];
#pragma unroll
    for (int c = 0; c < NC; c++) l[c] = d1 * (a[c] + y[c]) + sb4[c];

    float m = l[0];
#pragma unroll
    for (int c = 1; c < NC; c++) m = fmaxf(m, l[c]);
    float s = 0.f;
#pragma unroll
    for (int c = 0; c < NC; c++) s += expf(l[c] - m);
    float lse = m + logf(s);
#pragma unroll
    for (int c = 0; c < NC; c++) out[(size_t)i * NC + c] = l[c] - lse;
}

// ---------------- launch ----------------
extern "C" void kernel_launch(void* const* d_in, const int* in_sizes, int n_in,
                              void* d_out, int out_size) {
    const float* x  = (const float*)d_in[0];
    const int*   ei = (const int*)d_in[1];   // [2, NE] int32: row0 src, row1 dst
    const int*   tp = (const int*)d_in[2];
    const float* W1 = (const float*)d_in[3];
    const float* b1 = (const float*)d_in[4];
    const float* W2 = (const float*)d_in[5];
    const float* b2 = (const float*)d_in[6];
    const float* W4 = (const float*)d_in[7];
    const float* b4 = (const float*)d_in[8];
    float* out = (float*)d_out;

    k_zero<<<2048, 256>>>();
    k_degree<<<(2 * NE + 255) / 256, 256>>>(ei + NE, tp + NE);

    size_t smem = (size_t)(NF * 32 + 128 * 129) * sizeof(float);  // 82432 B
    cudaFuncSetAttribute(k_gemm, cudaFuncAttributeMaxDynamicSharedMemorySize, (int)smem);
    k_gemm<<<(NN + 127) / 128, 128, smem>>>(x, W1, W2);

    k_scatter16<<<(NE + 255) / 256, 256>>>(ei, ei + NE, 0);
    k_scatter16<<<(NE + 255) / 256, 256>>>(tp, tp + NE, 1);

    k_combine<<<(NN + 255) / 256, 256>>>(b1, b2, W4);

    k_scatter10<<<(NE + 255) / 256, 256>>>(ei, ei + NE);

    k_final<<<(NN + 255) / 256, 256>>>(b4, out);
}

// round 5
// speedup vs baseline: 2.7275x; 1.2672x over previous
#include <cuda_runtime.h>
#include <math.h>

#define NN 100000
#define NE 3200000
#define NF 128
#define HH 16
#define NC 10

// ---------------- device scratch (no runtime allocation allowed) ----------------
__device__ int   g_deg1[NN];
__device__ int   g_deg2[NN];
__device__ float g_dinv1[NN];
__device__ float g_dinv2[NN];
__device__ __align__(16) float g_y1[NN * 16];   // dinv1[i] * (x @ W1)[i]
__device__ __align__(16) float g_y2[NN * 16];   // dinv2[i] * (x @ W2)[i]
__device__ __align__(16) float g_acc1[NN * 16];
__device__ __align__(16) float g_acc2[NN * 16];
__device__ __align__(16) float g_yz[NN * 12];   // dinv1[i] * (h @ W4)[i], stride 12
__device__ __align__(16) float g_acc3[NN * 12];

// 16-byte vector reduction straight to L2 (sm_90+). Address forced to global space.
__device__ __forceinline__ void red_add_v4(float* p, float4 v) {
    asm volatile("red.global.add.v4.f32 [%0], {%1,%2,%3,%4};"
                 :: "l"(__cvta_generic_to_global(p)),
                    "f"(v.x), "f"(v.y), "f"(v.z), "f"(v.w)
                 : "memory");
}

// ---------------- zero scratch ----------------
__global__ void k_zero() {
    int i = blockIdx.x * blockDim.x + threadIdx.x;
    int stride = gridDim.x * blockDim.x;
    for (int t = i; t < NN; t += stride) { g_deg1[t] = 0; g_deg2[t] = 0; }
    for (int t = i; t < NN * 16; t += stride) { g_acc1[t] = 0.f; g_acc2[t] = 0.f; }
    for (int t = i; t < NN * 12; t += stride) g_acc3[t] = 0.f;
}

// ---------------- degrees (dst counts; self-loop folded in later as +1) ----------------
__global__ void k_degree(const int* __restrict__ dst1,
                         const int* __restrict__ dst2) {
    int e = blockIdx.x * blockDim.x + threadIdx.x;
    if (e < NE) {
        atomicAdd(&g_deg1[dst1[e]], 1);
    } else if (e < 2 * NE) {
        atomicAdd(&g_deg2[dst2[e - NE]], 1);
    }
}

// ---------------- fused dual GEMM: y1 = dinv1*(x@W1), y2 = dinv2*(x@W2) ----------------
__global__ void k_gemm(const float* __restrict__ x,
                       const float* __restrict__ W1,
                       const float* __restrict__ W2) {
    extern __shared__ float s_mem[];
    float* Ws = s_mem;              // [128][32]  (W1 cols 0..15, W2 cols 16..31)
    float* xs = s_mem + NF * 32;    // [128][129] padded

    int tid = threadIdx.x;
    for (int idx = tid; idx < NF * 32; idx += 128) {
        int k = idx >> 5, j = idx & 31;
        Ws[idx] = (j < HH) ? W1[k * HH + j] : W2[k * HH + (j - HH)];
    }
    int nb = blockIdx.x * 128;
    for (int idx = tid; idx < 128 * NF; idx += 128) {
        int node = idx >> 7, k = idx & 127;
        int gi = nb + node;
        xs[node * 129 + k] = (gi < NN) ? x[(size_t)gi * NF + k] : 0.f;
    }
    __syncthreads();

    int i = nb + tid;
    if (i >= NN) return;

    float acc[32];
#pragma unroll
    for (int j = 0; j < 32; j++) acc[j] = 0.f;

    const float* xr = &xs[tid * 129];
#pragma unroll 4
    for (int k = 0; k < NF; k++) {
        float xk = xr[k];
        const float* wrow = &Ws[k * 32];
#pragma unroll
        for (int j = 0; j < 32; j++) acc[j] += xk * wrow[j];
    }

    float d1 = rsqrtf((float)(g_deg1[i] + 1));
    float d2 = rsqrtf((float)(g_deg2[i] + 1));
    g_dinv1[i] = d1;
    g_dinv2[i] = d2;

    float* o1 = &g_y1[(size_t)i * 16];
    float* o2 = &g_y2[(size_t)i * 16];
#pragma unroll
    for (int j = 0; j < 16; j++) {
        o1[j] = d1 * acc[j];
        o2[j] = d2 * acc[16 + j];
    }
}

// ---------------- quad-per-edge scatter, 16-wide ------------------------------
// 4 consecutive lanes handle one edge; lane q covers channels [4q, 4q+4).
// A warp's single LDG.128 touches only 8 distinct 64B rows -> ~8 wavefronts
// (vs 32 in thread-per-edge layout).
__global__ void k_scatter16q(const int* __restrict__ src,
                             const int* __restrict__ dst,
                             const float* __restrict__ y,
                             float* __restrict__ acc) {
    unsigned t = blockIdx.x * blockDim.x + threadIdx.x;
    unsigned e = t >> 2;
    int q = t & 3;
    if (e >= NE) return;
    int s = src[e], d = dst[e];
    float4 v = *(const float4*)(y + (size_t)s * 16 + q * 4);
    red_add_v4(acc + (size_t)d * 16 + q * 4, v);
}

// ---------------- combine: relu epilogues, concat, h @ W4, pre-scale by dinv1 -----
__global__ void k_combine(const float* __restrict__ b1,
                          const float* __restrict__ b2,
                          const float* __restrict__ W4) {
    __shared__ float sW4[32 * NC];
    __shared__ float sb1[HH], sb2[HH];
    int tid = threadIdx.x;
    for (int t = tid; t < 32 * NC; t += blockDim.x) sW4[t] = W4[t];
    if (tid < HH) { sb1[tid] = b1[tid]; sb2[tid] = b2[tid]; }
    __syncthreads();

    int i = blockIdx.x * blockDim.x + tid;
    if (i >= NN) return;

    float d1 = g_dinv1[i], d2 = g_dinv2[i];
    float h[32];
    const float* a1 = &g_acc1[(size_t)i * 16];
    const float* y1 = &g_y1[(size_t)i * 16];
    const float* a2 = &g_acc2[(size_t)i * 16];
    const float* y2 = &g_y2[(size_t)i * 16];
#pragma unroll
    for (int j = 0; j < 16; j++) {
        h[j]      = fmaxf(d1 * (a1[j] + y1[j]) + sb1[j], 0.f);
        h[16 + j] = fmaxf(d2 * (a2[j] + y2[j]) + sb2[j], 0.f);
    }

    float z[NC];
#pragma unroll
    for (int c = 0; c < NC; c++) z[c] = 0.f;
#pragma unroll
    for (int j = 0; j < 32; j++) {
        float hj = h[j];
#pragma unroll
        for (int c = 0; c < NC; c++) z[c] += hj * sW4[j * NC + c];
    }

    float* o = &g_yz[(size_t)i * 12];
#pragma unroll
    for (int c = 0; c < NC; c++) o[c] = d1 * z[c];
    o[10] = 0.f;
    o[11] = 0.f;
}

// ---------------- 3-lanes-per-edge scatter for 12-padded logits -------------------
__global__ void k_scatter10q(const int* __restrict__ src,
                             const int* __restrict__ dst) {
    unsigned t = blockIdx.x * blockDim.x + threadIdx.x;
    unsigned e = t / 3u;            // mul-shift, cheap
    int q = (int)(t - e * 3u);
    if (e >= NE) return;
    int s = src[e], d = dst[e];
    float4 v = *(const float4*)(&g_yz[(size_t)s * 12] + q * 4);
    red_add_v4(&g_acc3[(size_t)d * 12] + q * 4, v);   // lanes 10,11 add 0.0f padding
}

// ---------------- final: conv3 epilogue + log_softmax ----------------
__global__ void k_final(const float* __restrict__ b4, float* __restrict__ out) {
    __shared__ float sb4[NC];
    if (threadIdx.x < NC) sb4[threadIdx.x] = b4[threadIdx.x];
    __syncthreads();
    int i = blockIdx.x * blockDim.x + threadIdx.x;
    if (i >= NN) return;

    float d1 = g_dinv1[i];
    float l[NC];
    const float* a = &g_acc3[(size_t)i * 12];
    const float* y = &g_yz[(size_t)i * 12];
#pragma unroll
    for (int c = 0; c < NC; c++) l[c] = d1 * (a[c] + y[c]) + sb4[c];

    float m = l[0];
#pragma unroll
    for (int c = 1; c < NC; c++) m = fmaxf(m, l[c]);
    float s = 0.f;
#pragma unroll
    for (int c = 0; c < NC; c++) s += expf(l[c] - m);
    float lse = m + logf(s);
#pragma unroll
    for (int c = 0; c < NC; c++) out[(size_t)i * NC + c] = l[c] - lse;
}

// ---------------- launch ----------------
extern "C" void kernel_launch(void* const* d_in, const int* in_sizes, int n_in,
                              void* d_out, int out_size) {
    const float* x  = (const float*)d_in[0];
    const int*   ei = (const int*)d_in[1];   // [2, NE] int32: row0 src, row1 dst
    const int*   tp = (const int*)d_in[2];
    const float* W1 = (const float*)d_in[3];
    const float* b1 = (const float*)d_in[4];
    const float* W2 = (const float*)d_in[5];
    const float* b2 = (const float*)d_in[6];
    const float* W4 = (const float*)d_in[7];
    const float* b4 = (const float*)d_in[8];
    float* out = (float*)d_out;

    // device-global scratch pointers for parameterized kernels
    float *p_y1, *p_y2, *p_a1, *p_a2;
    cudaGetSymbolAddress((void**)&p_y1, g_y1);
    cudaGetSymbolAddress((void**)&p_y2, g_y2);
    cudaGetSymbolAddress((void**)&p_a1, g_acc1);
    cudaGetSymbolAddress((void**)&p_a2, g_acc2);

    k_zero<<<2048, 256>>>();
    k_degree<<<(2 * NE + 255) / 256, 256>>>(ei + NE, tp + NE);

    size_t smem = (size_t)(NF * 32 + 128 * 129) * sizeof(float);  // 82432 B
    cudaFuncSetAttribute(k_gemm, cudaFuncAttributeMaxDynamicSharedMemorySize, (int)smem);
    k_gemm<<<(NN + 127) / 128, 128, smem>>>(x, W1, W2);

    // quad-per-edge scatters: 4*NE lanes each
    k_scatter16q<<<(4u * NE + 255) / 256, 256>>>(ei, ei + NE, p_y1, p_a1);
    k_scatter16q<<<(4u * NE + 255) / 256, 256>>>(tp, tp + NE, p_y2, p_a2);

    k_combine<<<(NN + 255) / 256, 256>>>(b1, b2, W4);

    k_scatter10q<<<(3u * NE + 255) / 256, 256>>>(ei, ei + NE);

    k_final<<<(NN + 255) / 256, 256>>>(b4, out);
}